// round 6
// baseline (speedup 1.0000x reference)
#include <cuda_runtime.h>

#define NMAX 100000
#define EMAX 1500000

// Static scratch (allocation-free rule).
static __device__ __align__(16) float g_agg[NMAX * 64];   // 25.6 MB
static __device__ __align__(8)  int2  g_pairs[EMAX];      // {src, w bits} 12 MB
static __device__ int g_counts[NMAX];
static __device__ int g_offsets[NMAX];
static __device__ int g_cursor[NMAX];
static __device__ int g_blocksums[128];                    // ceil(NMAX/1024)=98
static __device__ int g_idx_is64;

// ---------------------------------------------------------------------------
// Parallel dtype detect (JAX demotes int64->int32 when x64 disabled).
// 32 samples in one memory round-trip + ballot.
// ---------------------------------------------------------------------------
__global__ void detect_idx_dtype_kernel(const long long* __restrict__ ei,
                                        int E, int n_src)
{
    int i = threadIdx.x;                       // 32 threads
    long long stride = (E > 32) ? (E / 32) : 1;
    long long idx = (long long)i * stride;
    if (idx > E - 1) idx = E - 1;
    long long v = ei[idx];
    bool bad = (v < 0 || v >= n_src);
    unsigned m = __ballot_sync(0xffffffffu, bad);
    if (i == 0) g_idx_is64 = (m == 0) ? 1 : 0;
}

// ---------------------------------------------------------------------------
// Histogram of dst indices.
// ---------------------------------------------------------------------------
__global__ void hist_kernel(const void* __restrict__ ei_raw, int E)
{
    int e = blockIdx.x * blockDim.x + threadIdx.x;
    if (e >= E) return;
    int d = g_idx_is64 ? (int)((const long long*)ei_raw)[(long long)E + e]
                       : ((const int*)ei_raw)[(long long)E + e];
    atomicAdd(&g_counts[d], 1);
}

// ---------------------------------------------------------------------------
// Per-1024-chunk reduction of counts -> g_blocksums.
// ---------------------------------------------------------------------------
__global__ void __launch_bounds__(1024) blockreduce_kernel(int n)
{
    __shared__ int sdata[1024];
    int i = blockIdx.x * 1024 + threadIdx.x;
    sdata[threadIdx.x] = (i < n) ? g_counts[i] : 0;
    __syncthreads();
    #pragma unroll
    for (int s = 512; s > 0; s >>= 1) {
        if (threadIdx.x < s) sdata[threadIdx.x] += sdata[threadIdx.x + s];
        __syncthreads();
    }
    if (threadIdx.x == 0) g_blocksums[blockIdx.x] = sdata[0];
}

// ---------------------------------------------------------------------------
// Exclusive scan of block sums (<=128 values; serial in L1, trivial).
// ---------------------------------------------------------------------------
__global__ void scan_sums_kernel(int nb)
{
    if (threadIdx.x == 0 && blockIdx.x == 0) {
        int acc = 0;
        for (int b = 0; b < nb; b++) {
            int v = g_blocksums[b];
            g_blocksums[b] = acc;
            acc += v;
        }
    }
}

// ---------------------------------------------------------------------------
// Per-chunk exclusive scan + chunk offset -> offsets, cursor.
// ---------------------------------------------------------------------------
__global__ void __launch_bounds__(1024) blockscan_kernel(int n)
{
    __shared__ int sdata[1024];
    int i = blockIdx.x * 1024 + threadIdx.x;
    int v = (i < n) ? g_counts[i] : 0;
    sdata[threadIdx.x] = v;
    __syncthreads();
    #pragma unroll
    for (int s = 1; s < 1024; s <<= 1) {
        int t = (threadIdx.x >= s) ? sdata[threadIdx.x - s] : 0;
        __syncthreads();
        sdata[threadIdx.x] += t;
        __syncthreads();
    }
    if (i < n) {
        int excl = sdata[threadIdx.x] - v + g_blocksums[blockIdx.x];
        g_offsets[i] = excl;
        g_cursor[i]  = excl;
    }
}

// ---------------------------------------------------------------------------
// Reorder edges into dst-contiguous pairs {src, w}.
// ---------------------------------------------------------------------------
__global__ void reorder_kernel(const void* __restrict__ ei_raw,
                               const float* __restrict__ ew, int E)
{
    int e = blockIdx.x * blockDim.x + threadIdx.x;
    if (e >= E) return;
    int s, d;
    if (g_idx_is64) {
        const long long* ei = (const long long*)ei_raw;
        s = (int)ei[e]; d = (int)ei[(long long)E + e];
    } else {
        const int* ei = (const int*)ei_raw;
        s = ei[e]; d = ei[(long long)E + e];
    }
    int pos = atomicAdd(&g_cursor[d], 1);
    g_pairs[pos] = make_int2(s, __float_as_int(ew[e]));
}

// ---------------------------------------------------------------------------
// Atomic-free accumulate: agg[dst] = sum over its edges of w * x_src[src].
// 16 lanes per dst (2 dsts per warp); each lane owns one float4 column slot.
// Pairs loaded coalesced (lane j -> edge j), broadcast via group-masked shfl.
// Writes every row (cnt==0 -> zeros), so agg needs no memset.
// ---------------------------------------------------------------------------
__global__ void __launch_bounds__(256) accumulate_kernel(
    const float* __restrict__ xsrc, int n_dst)
{
    const int t = blockIdx.x * blockDim.x + threadIdx.x;
    const int lane = t & 15;
    const int dst  = t >> 4;
    if (dst >= n_dst) return;

    const int off = g_offsets[dst];
    const int cnt = g_counts[dst];
    const unsigned gmask = 0xFFFFu << (threadIdx.x & 16);
    const int gbase = threadIdx.x & 16;

    float4 acc = make_float4(0.f, 0.f, 0.f, 0.f);
    for (int base = 0; base < cnt; base += 16) {
        const int m = (cnt - base < 16) ? (cnt - base) : 16;
        int2 p = (lane < m) ? g_pairs[off + base + lane] : make_int2(0, 0);
        for (int j = 0; j < m; j++) {
            int   sj = __shfl_sync(gmask, p.x, gbase + j, 32);
            float wj = __int_as_float(__shfl_sync(gmask, p.y, gbase + j, 32));
            float4 v = *(const float4*)(xsrc + (size_t)sj * 64 + lane * 4);
            acc.x = fmaf(v.x, wj, acc.x);
            acc.y = fmaf(v.y, wj, acc.y);
            acc.z = fmaf(v.z, wj, acc.z);
            acc.w = fmaf(v.w, wj, acc.w);
        }
    }
    *(float4*)(g_agg + (size_t)dst * 64 + lane * 4) = acc;
}

// ---------------------------------------------------------------------------
// Fallback atomic scatter (input space), used only if sizes exceed capacity.
// ---------------------------------------------------------------------------
__global__ void __launch_bounds__(256) scatter_atomic_kernel(
    const float* __restrict__ xsrc, const void* __restrict__ ei_raw,
    const float* __restrict__ ew, float* __restrict__ agg, int E)
{
    const long long t = (long long)blockIdx.x * blockDim.x + threadIdx.x;
    const int lane = (int)(t & 15);
    const long long e0 = (t >> 4) * 4;
    if (e0 >= E) return;
    const int n = (E - e0 >= 4) ? 4 : (int)(E - e0);

    long long s[4], d[4];
    float w[4];
    if (g_idx_is64) {
        const long long* ei = (const long long*)ei_raw;
        #pragma unroll
        for (int i = 0; i < 4; i++) if (i < n) {
            s[i] = ei[e0 + i]; d[i] = ei[(long long)E + e0 + i];
        }
    } else {
        const int* ei = (const int*)ei_raw;
        #pragma unroll
        for (int i = 0; i < 4; i++) if (i < n) {
            s[i] = ei[e0 + i]; d[i] = ei[(long long)E + e0 + i];
        }
    }
    #pragma unroll
    for (int i = 0; i < 4; i++) if (i < n) w[i] = ew[e0 + i];
    #pragma unroll
    for (int i = 0; i < 4; i++) if (i < n) {
        float4 v = *(const float4*)(xsrc + s[i] * 64 + lane * 4);
        v.x *= w[i]; v.y *= w[i]; v.z *= w[i]; v.w *= w[i];
        float* dp = agg + d[i] * 64 + lane * 4;
        asm volatile("red.global.add.v4.f32 [%0], {%1, %2, %3, %4};"
                     :: "l"(dp), "f"(v.x), "f"(v.y), "f"(v.z), "f"(v.w)
                     : "memory");
    }
}

// ---------------------------------------------------------------------------
// Fused GEMM (round-4 proven layout, two K=64 halves):
//   out = x_dst @ W_self^T + g_agg @ W_nei^T + b      (N x 64)
// Block = 256 thr = 16x16; block tile 64x64; thread tile 4x4; XOR-swizzled
// shared tiles (chunk = kq ^ (row&15)) -> conflict-optimal LDS.128.
// ---------------------------------------------------------------------------
__global__ void __launch_bounds__(256) fused_gemm_kernel(
    const float* __restrict__ Xd, const float* __restrict__ Wself,
    const float* __restrict__ Wnei, const float* __restrict__ bias,
    float* __restrict__ out, int N)
{
    __shared__ __align__(16) float Xs[64][64];
    __shared__ __align__(16) float Ws[2][64][64];

    const int tid = threadIdx.x;
    const int tx = tid & 15;
    const int ty = tid >> 4;
    const int rowbase = blockIdx.x * 64;

    #pragma unroll
    for (int m = 0; m < 2; m++) {
        const float* Wm = m ? Wnei : Wself;
        #pragma unroll
        for (int i = 0; i < 4; i++) {
            int f  = tid + i * 256;
            int c  = f >> 4;
            int kq = f & 15;
            float4 v = *(const float4*)(Wm + c * 64 + kq * 4);
            *(float4*)&Ws[m][c][(kq ^ (c & 15)) * 4] = v;
        }
    }

    float acc[4][4];
    #pragma unroll
    for (int i = 0; i < 4; i++)
        #pragma unroll
        for (int j = 0; j < 4; j++) acc[i][j] = 0.f;

    const float* aggp = g_agg;

    #pragma unroll 1
    for (int h = 0; h < 2; h++) {
        const float* Xsrc = h ? aggp : Xd;
        __syncthreads();   // h=0: Ws staged; h=1: Xs readers done
        #pragma unroll
        for (int i = 0; i < 4; i++) {
            int f  = tid + i * 256;
            int r  = f >> 4;
            int kq = f & 15;
            int gr = rowbase + r;
            float4 v = make_float4(0.f, 0.f, 0.f, 0.f);
            if (gr < N) v = *(const float4*)(Xsrc + (size_t)gr * 64 + kq * 4);
            *(float4*)&Xs[r][(kq ^ (r & 15)) * 4] = v;
        }
        __syncthreads();

        #pragma unroll
        for (int kq = 0; kq < 16; kq++) {
            const int kx = (kq ^ ty) * 4;
            const int kw = (kq ^ tx) * 4;
            float4 xv[4], wv[4];
            #pragma unroll
            for (int i = 0; i < 4; i++) xv[i] = *(const float4*)&Xs[ty + 16 * i][kx];
            #pragma unroll
            for (int j = 0; j < 4; j++) wv[j] = *(const float4*)&Ws[h][tx + 16 * j][kw];
            #pragma unroll
            for (int i = 0; i < 4; i++)
                #pragma unroll
                for (int j = 0; j < 4; j++) {
                    acc[i][j] = fmaf(xv[i].x, wv[j].x, acc[i][j]);
                    acc[i][j] = fmaf(xv[i].y, wv[j].y, acc[i][j]);
                    acc[i][j] = fmaf(xv[i].z, wv[j].z, acc[i][j]);
                    acc[i][j] = fmaf(xv[i].w, wv[j].w, acc[i][j]);
                }
        }
    }

    float bval[4];
    #pragma unroll
    for (int j = 0; j < 4; j++) bval[j] = bias[tx + 16 * j];

    #pragma unroll
    for (int i = 0; i < 4; i++) {
        const int gr = rowbase + ty + 16 * i;
        if (gr < N) {
            float* yrow = out + (size_t)gr * 64;
            #pragma unroll
            for (int j = 0; j < 4; j++)
                yrow[tx + 16 * j] = acc[i][j] + bval[j];
        }
    }
}

// ---------------------------------------------------------------------------
// Inputs: 0:x_src f32[Ns*64] 1:x_dst f32[Nd*64] 2:edge_index[2E] (i32/i64)
//         3:edge_weight f32[E] 4:W_nei [64,64] 5:W_self [64,64] 6:b_self [64]
// Output: f32 [Nd*64]
// ---------------------------------------------------------------------------
extern "C" void kernel_launch(void* const* d_in, const int* in_sizes, int n_in,
                              void* d_out, int out_size)
{
    const float* x_src  = (const float*)d_in[0];
    const float* x_dst  = (const float*)d_in[1];
    const void*  ei     = d_in[2];
    const float* ew     = (const float*)d_in[3];
    const float* W_nei  = (const float*)d_in[4];
    const float* W_self = (const float*)d_in[5];
    const float* b_self = (const float*)d_in[6];
    float*       out    = (float*)d_out;

    const int n_src = in_sizes[0] / 64;
    const int n_dst = in_sizes[1] / 64;
    const int E     = in_sizes[3];

    detect_idx_dtype_kernel<<<1, 32>>>((const long long*)ei, E, n_src);

    if (E <= EMAX && n_dst <= NMAX) {
        // ---- CSR path (atomic-free accumulate) ----
        int* countsp = nullptr;
        cudaGetSymbolAddress((void**)&countsp, g_counts);
        cudaMemsetAsync(countsp, 0, (size_t)n_dst * sizeof(int));

        hist_kernel<<<(E + 255) / 256, 256>>>(ei, E);

        const int NB = (n_dst + 1023) / 1024;
        blockreduce_kernel<<<NB, 1024>>>(n_dst);
        scan_sums_kernel<<<1, 32>>>(NB);
        blockscan_kernel<<<NB, 1024>>>(n_dst);

        reorder_kernel<<<(E + 255) / 256, 256>>>(ei, ew, E);

        {
            long long threads = (long long)n_dst * 16;
            int blocks = (int)((threads + 255) / 256);
            accumulate_kernel<<<blocks, 256>>>(x_src, n_dst);
        }
    } else {
        // ---- fallback: atomic scatter into zeroed agg ----
        float* aggp = nullptr;
        cudaGetSymbolAddress((void**)&aggp, g_agg);
        cudaMemsetAsync(aggp, 0, (size_t)n_dst * 64 * sizeof(float));
        long long groups  = ((long long)E + 3) / 4;
        long long threads = groups * 16;
        int blocks = (int)((threads + 255) / 256);
        scatter_atomic_kernel<<<blocks, 256>>>(x_src, ei, ew, aggp, E);
    }

    fused_gemm_kernel<<<(n_dst + 63) / 64, 256>>>(
        x_dst, W_self, W_nei, b_self, out, n_dst);
}

// round 7
// speedup vs baseline: 1.4500x; 1.4500x over previous
#include <cuda_runtime.h>

#define NMAX 100000

// Aggregation buffer agg[dst] = sum_e w_e * x_src[src_e]; 25.6 MB static.
static __device__ __align__(16) float g_agg[NMAX * 64];
static __device__ int g_idx_is64;

// ---------------------------------------------------------------------------
// Parallel dtype detect (JAX demotes int64->int32 when x64 disabled).
// ---------------------------------------------------------------------------
__global__ void detect_idx_dtype_kernel(const long long* __restrict__ ei,
                                        int E, int n_src)
{
    int i = threadIdx.x;                       // 32 threads
    long long stride = (E > 32) ? (E / 32) : 1;
    long long idx = (long long)i * stride;
    if (idx > E - 1) idx = E - 1;
    long long v = ei[idx];
    bool bad = (v < 0 || v >= n_src);
    unsigned m = __ballot_sync(0xffffffffu, bad);
    if (i == 0) g_idx_is64 = (m == 0) ? 1 : 0;
}

// ---------------------------------------------------------------------------
// Edge scatter (input space): g_agg[dst] += x_src[src] * w.
// 16 lanes per edge-group; each thread owns one float4 slot of 8 consecutive
// edges -> 8 independent L2 gathers in flight (MLP=8), then 8 vector REDs.
// ---------------------------------------------------------------------------
__global__ void __launch_bounds__(256) scatter_kernel(
    const float* __restrict__ xsrc,
    const void* __restrict__ ei_raw,    // [2, E]: src row then dst row
    const float* __restrict__ ew,       // [E]
    int E)
{
    const long long t = (long long)blockIdx.x * blockDim.x + threadIdx.x;
    const int lane = (int)(t & 15);
    const long long e0 = (t >> 4) * 8;
    if (e0 >= E) return;
    const int n = (E - e0 >= 8) ? 8 : (int)(E - e0);

    int s[8], d[8];
    float w[8];
    if (g_idx_is64) {
        const long long* ei = (const long long*)ei_raw;
        #pragma unroll
        for (int i = 0; i < 8; i++) if (i < n) {
            s[i] = (int)ei[e0 + i];
            d[i] = (int)ei[(long long)E + e0 + i];
        }
    } else {
        const int* ei = (const int*)ei_raw;
        #pragma unroll
        for (int i = 0; i < 8; i++) if (i < n) {
            s[i] = ei[e0 + i];
            d[i] = ei[(long long)E + e0 + i];
        }
    }
    #pragma unroll
    for (int i = 0; i < 8; i++) if (i < n) w[i] = ew[e0 + i];

    float4 v[8];
    #pragma unroll
    for (int i = 0; i < 8; i++) if (i < n)
        v[i] = *(const float4*)(xsrc + (size_t)s[i] * 64 + lane * 4);

    #pragma unroll
    for (int i = 0; i < 8; i++) if (i < n) {
        const float wi = w[i];
        float4 vv = v[i];
        vv.x *= wi; vv.y *= wi; vv.z *= wi; vv.w *= wi;
        float* dst = g_agg + (size_t)d[i] * 64 + lane * 4;
        asm volatile("red.global.add.v4.f32 [%0], {%1, %2, %3, %4};"
                     :: "l"(dst), "f"(vv.x), "f"(vv.y), "f"(vv.z), "f"(vv.w)
                     : "memory");
    }
}

// ---------------------------------------------------------------------------
// tf32 helpers
// ---------------------------------------------------------------------------
__device__ __forceinline__ unsigned f2tf32(float x) {
    unsigned u;
    asm("cvt.rna.tf32.f32 %0, %1;" : "=r"(u) : "f"(x));
    return u;
}

#define MMA_TF32(c0, c1, c2, c3, a0, a1, a2, a3, b0, b1)                     \
    asm volatile(                                                            \
        "mma.sync.aligned.m16n8k8.row.col.f32.tf32.tf32.f32 "               \
        "{%0,%1,%2,%3}, {%4,%5,%6,%7}, {%8,%9}, {%0,%1,%2,%3};"             \
        : "+f"(c0), "+f"(c1), "+f"(c2), "+f"(c3)                             \
        : "r"(a0), "r"(a1), "r"(a2), "r"(a3), "r"(b0), "r"(b1))

// ---------------------------------------------------------------------------
// Fused tf32 GEMM: out = x_dst @ W_self^T + g_agg @ W_nei^T + b   (N x 64)
// Logical A = [x_dst | agg] (N x 128), B[k][c] = Wself[c][k] (k<64) /
// Wnei[c][k-64]. Block = 256 thr (8 warps); block tile 128 rows x 64 cols;
// warp w owns rows 16w..16w+15 x all 64 cols (8 n-tiles of m16n8k8).
// Shared: As[128][68] (pad 68 -> frag loads bank-free: (4g+t) distinct),
//         Bs[64][132] = W[c][k] both halves (pad 132 -> same property).
// ---------------------------------------------------------------------------
#define AS_STRIDE 68
#define BS_STRIDE 132
#define AS_FLOATS (128 * AS_STRIDE)
#define BS_FLOATS (64 * BS_STRIDE)
#define GEMM_SMEM_BYTES ((AS_FLOATS + BS_FLOATS) * 4)

__global__ void __launch_bounds__(256) fused_gemm_tf32_kernel(
    const float* __restrict__ Xd, const float* __restrict__ Wself,
    const float* __restrict__ Wnei, const float* __restrict__ bias,
    float* __restrict__ out, int N)
{
    extern __shared__ __align__(16) float smem[];
    float* As = smem;                 // [128][AS_STRIDE]
    float* Bs = smem + AS_FLOATS;     // [64][BS_STRIDE], cols 0..127 = k

    const int tid  = threadIdx.x;
    const int lane = tid & 31;
    const int wid  = tid >> 5;        // 0..7
    const int g    = lane >> 2;       // groupID 0..7
    const int tg   = lane & 3;        // thread-in-group 0..3
    const int wr   = wid * 16;        // warp row base within tile
    const int rowbase = blockIdx.x * 128;

    // ---- stage B (both W matrices), cvt to tf32 bits ----
    #pragma unroll
    for (int m = 0; m < 2; m++) {
        const float* Wm = m ? Wnei : Wself;
        #pragma unroll
        for (int i = 0; i < 4; i++) {
            int f  = tid + i * 256;            // float4 id 0..1023
            int c  = f >> 4;                   // 0..63
            int k4 = f & 15;
            float4 v = *(const float4*)(Wm + c * 64 + k4 * 4);
            float* b = Bs + c * BS_STRIDE + m * 64 + k4 * 4;
            b[0] = __uint_as_float(f2tf32(v.x));
            b[1] = __uint_as_float(f2tf32(v.y));
            b[2] = __uint_as_float(f2tf32(v.z));
            b[3] = __uint_as_float(f2tf32(v.w));
        }
    }

    // ---- init accumulators with bias ----
    // acc[nt]: c0=(row g, col nt*8+2tg) c1=(+1 col) c2/c3=(row g+8)
    float acc[8][4];
    #pragma unroll
    for (int nt = 0; nt < 8; nt++) {
        float b0 = bias[nt * 8 + 2 * tg];
        float b1 = bias[nt * 8 + 2 * tg + 1];
        acc[nt][0] = b0; acc[nt][1] = b1;
        acc[nt][2] = b0; acc[nt][3] = b1;
    }

    const float* aggp = g_agg;

    #pragma unroll 1
    for (int h = 0; h < 2; h++) {
        const float* Xsrc = h ? aggp : Xd;
        __syncthreads();   // h=0: Bs staged; h=1: As readers done
        // ---- stage As: 128 rows x 64 k (8 float4 per thread), cvt tf32 ----
        #pragma unroll
        for (int i = 0; i < 8; i++) {
            int f  = tid + i * 256;            // 0..2047
            int r  = f >> 4;
            int k4 = f & 15;
            int gr = rowbase + r;
            float4 v = make_float4(0.f, 0.f, 0.f, 0.f);
            if (gr < N) v = *(const float4*)(Xsrc + (size_t)gr * 64 + k4 * 4);
            float4 cv;
            cv.x = __uint_as_float(f2tf32(v.x));
            cv.y = __uint_as_float(f2tf32(v.y));
            cv.z = __uint_as_float(f2tf32(v.z));
            cv.w = __uint_as_float(f2tf32(v.w));
            *(float4*)(As + r * AS_STRIDE + k4 * 4) = cv;
        }
        __syncthreads();

        #pragma unroll
        for (int kc = 0; kc < 8; kc++) {       // k-chunks of 8
            const int k0 = kc * 8;
            const float* arow0 = As + (wr + g) * AS_STRIDE + k0;
            const float* arow1 = arow0 + 8 * AS_STRIDE;
            unsigned a0 = __float_as_uint(arow0[tg]);
            unsigned a1 = __float_as_uint(arow1[tg]);
            unsigned a2 = __float_as_uint(arow0[tg + 4]);
            unsigned a3 = __float_as_uint(arow1[tg + 4]);
            #pragma unroll
            for (int nt = 0; nt < 8; nt++) {
                const float* brow = Bs + (nt * 8 + g) * BS_STRIDE + h * 64 + k0;
                unsigned b0 = __float_as_uint(brow[tg]);
                unsigned b1 = __float_as_uint(brow[tg + 4]);
                MMA_TF32(acc[nt][0], acc[nt][1], acc[nt][2], acc[nt][3],
                         a0, a1, a2, a3, b0, b1);
            }
        }
    }

    // ---- store: rows wr+g and wr+g+8, cols nt*8 + 2tg (+1) ----
    const int r0 = rowbase + wr + g;
    const int r1 = r0 + 8;
    if (r0 < N) {
        float* yrow = out + (size_t)r0 * 64;
        #pragma unroll
        for (int nt = 0; nt < 8; nt++)
            *(float2*)(yrow + nt * 8 + 2 * tg) = make_float2(acc[nt][0], acc[nt][1]);
    }
    if (r1 < N) {
        float* yrow = out + (size_t)r1 * 64;
        #pragma unroll
        for (int nt = 0; nt < 8; nt++)
            *(float2*)(yrow + nt * 8 + 2 * tg) = make_float2(acc[nt][2], acc[nt][3]);
    }
}

// ---------------------------------------------------------------------------
// Inputs: 0:x_src f32[Ns*64] 1:x_dst f32[Nd*64] 2:edge_index[2E] (i32/i64)
//         3:edge_weight f32[E] 4:W_nei [64,64] 5:W_self [64,64] 6:b_self [64]
// Output: f32 [Nd*64]
// ---------------------------------------------------------------------------
extern "C" void kernel_launch(void* const* d_in, const int* in_sizes, int n_in,
                              void* d_out, int out_size)
{
    const float* x_src  = (const float*)d_in[0];
    const float* x_dst  = (const float*)d_in[1];
    const void*  ei     = d_in[2];
    const float* ew     = (const float*)d_in[3];
    const float* W_nei  = (const float*)d_in[4];
    const float* W_self = (const float*)d_in[5];
    const float* b_self = (const float*)d_in[6];
    float*       out    = (float*)d_out;

    const int n_src = in_sizes[0] / 64;
    const int n_dst = in_sizes[1] / 64;
    const int E     = in_sizes[3];

    float* aggp = nullptr;
    cudaGetSymbolAddress((void**)&aggp, g_agg);

    // 0) zero agg + detect index dtype
    cudaMemsetAsync(aggp, 0, (size_t)n_dst * 64 * sizeof(float));
    detect_idx_dtype_kernel<<<1, 32>>>((const long long*)ei, E, n_src);

    // 1) scatter in input space (8 edges per thread, 16 lanes/edge)
    {
        long long groups  = ((long long)E + 7) / 8;
        long long threads = groups * 16;
        int blocks = (int)((threads + 255) / 256);
        scatter_kernel<<<blocks, 256>>>(x_src, ei, ew, E);
    }

    // 2) fused tf32 GEMM: out = x_dst @ W_self^T + agg @ W_nei^T + b
    static int smem_set = 0;
    if (!smem_set) {
        cudaFuncSetAttribute(fused_gemm_tf32_kernel,
                             cudaFuncAttributeMaxDynamicSharedMemorySize,
                             GEMM_SMEM_BYTES);
        smem_set = 1;
    }
    fused_gemm_tf32_kernel<<<(n_dst + 127) / 128, 256, GEMM_SMEM_BYTES>>>(
        x_dst, W_self, W_nei, b_self, out, n_dst);
}